// round 8
// baseline (speedup 1.0000x reference)
#include <cuda_runtime.h>
#include <cuda.h>
#include <cuda_fp16.h>
#include <cuda_bf16.h>
#include <cstdint>

#define M_TOTAL 4096
#define N_TOTAL 4096
#define K_TOTAL 4096
#define GROUP_SIZE 128
#define NGROUPS (K_TOTAL / GROUP_SIZE)   // 32

// Arch-specific feature gate (tcgen05/TMEM/TMA-multicast are sm_103a-only).
#if defined(__CUDA_ARCH_FEAT_SM103_ALL) || defined(__CUDA_ARCH_FEAT_SM100_ALL) || \
    (defined(__CUDA_ARCH_SPECIFIC__) && (__CUDA_ARCH_SPECIFIC__ >= 1000))
#define HAS_TCGEN05 1
#else
#define HAS_TCGEN05 0
#endif

// Scratch (device globals: allocation-free rule)
__device__ __half g_Wd[(size_t)N_TOTAL * K_TOTAL];   // dequantized weights fp16 [N,K]
__device__ __half g_X[(size_t)M_TOTAL * K_TOTAL];    // activations fp16 [M,K] (non-f16 input only)
__device__ int    g_dtype;                           // 0=f16, 1=f32, 2=bf16

// ===========================================================================
// PTX helpers
// ===========================================================================
__device__ __forceinline__ uint32_t elect_one_pred() {
    uint32_t pred;
    asm volatile(
        "{\n\t.reg .pred p;\n\telect.sync _|p, 0xFFFFFFFF;\n\t"
        "selp.b32 %0, 1, 0, p;\n\t}"
        : "=r"(pred));
    return pred;
}
__device__ __forceinline__ uint32_t smem_to_u32(const void* p) {
    uint32_t a;
    asm("{ .reg .u64 t; cvta.to.shared.u64 t, %1; cvt.u32.u64 %0, t; }" : "=r"(a) : "l"(p));
    return a;
}

#define MBARRIER_INIT(addr, cnt) \
    asm volatile("mbarrier.init.shared.b64 [%0], %1;" :: "r"((uint32_t)(addr)), "r"((uint32_t)(cnt)) : "memory")
#define MBARRIER_EXPECT_TX(addr, bytes) \
    asm volatile("mbarrier.arrive.expect_tx.shared.b64 _, [%0], %1;" :: "r"((uint32_t)(addr)), "r"((uint32_t)(bytes)) : "memory")

#define MBARRIER_WAIT_PARITY(mbar_addr, phase_parity) do { \
    uint32_t _mbar = (uint32_t)(mbar_addr); \
    uint32_t _par = (uint32_t)(phase_parity); \
    uint32_t _done; \
    asm volatile("{\n\t.reg .pred p;\n\t" \
        "mbarrier.try_wait.parity.acquire.cta.shared::cta.b64 p, [%1], %2;\n\t" \
        "selp.b32 %0, 1, 0, p;\n\t}" : "=r"(_done) : "r"(_mbar), "r"(_par) : "memory"); \
    if (!_done) { \
        asm volatile("{\n\t.reg .pred P1;\n\t" \
            "WAIT_LOOP_%=:\n\t" \
            "mbarrier.try_wait.parity.acquire.cta.shared::cta.b64 P1, [%0], %1, 0x989680;\n\t" \
            "@P1 bra.uni WAIT_DONE_%=;\n\t" \
            "bra.uni WAIT_LOOP_%=;\n\t" \
            "WAIT_DONE_%=:\n\t}" :: "r"(_mbar), "r"(_par) : "memory"); \
    } \
} while(0)

#define CLUSTER_SYNC() do { \
    asm volatile("barrier.cluster.arrive.aligned;" ::: "memory"); \
    asm volatile("barrier.cluster.wait.aligned;" ::: "memory"); \
} while(0)

#if HAS_TCGEN05
#define TCGEN05_ALLOC(smem_addr, nCols) \
    asm volatile("tcgen05.alloc.cta_group::1.sync.aligned.shared::cta.b32 [%0], %1;" \
        :: "r"((uint32_t)(smem_addr)), "r"((uint32_t)(nCols)) : "memory")
#define TCGEN05_DEALLOC(tmem_addr, nCols) \
    asm volatile("tcgen05.dealloc.cta_group::1.sync.aligned.b32 %0, %1;" :: "r"(tmem_addr), "r"((uint32_t)(nCols)))
#define TCGEN05_RELINQUISH() \
    asm volatile("tcgen05.relinquish_alloc_permit.cta_group::1.sync.aligned;")
#define TCGEN05_COMMIT_MULTICAST(mbar, mask) \
    asm volatile("tcgen05.commit.cta_group::1.mbarrier::arrive::one.shared::cluster.multicast::cluster.b64 [%0], %1;" \
        :: "r"((uint32_t)(mbar)), "h"((uint16_t)(mask)) : "memory")
#define TCGEN05_FENCE_AFTER() \
    asm volatile("tcgen05.fence::after_thread_sync;" ::: "memory")
#define TCGEN05_FENCE_BEFORE() \
    asm volatile("tcgen05.fence::before_thread_sync;" ::: "memory")
#define TCGEN05_WAIT_LD() \
    asm volatile("tcgen05.wait::ld.sync.aligned;" ::: "memory")

#define TCGEN05_LD_32X32B_X32(r, tmem_addr) \
    asm volatile( \
        "tcgen05.ld.sync.aligned.32x32b.x32.b32 " \
        "{%0, %1, %2, %3, %4, %5, %6, %7, " \
        " %8, %9, %10, %11, %12, %13, %14, %15, " \
        " %16, %17, %18, %19, %20, %21, %22, %23, " \
        " %24, %25, %26, %27, %28, %29, %30, %31}, [%32];" \
        : "=r"((r)[0]),  "=r"((r)[1]),  "=r"((r)[2]),  "=r"((r)[3]), \
          "=r"((r)[4]),  "=r"((r)[5]),  "=r"((r)[6]),  "=r"((r)[7]), \
          "=r"((r)[8]),  "=r"((r)[9]),  "=r"((r)[10]), "=r"((r)[11]), \
          "=r"((r)[12]), "=r"((r)[13]), "=r"((r)[14]), "=r"((r)[15]), \
          "=r"((r)[16]), "=r"((r)[17]), "=r"((r)[18]), "=r"((r)[19]), \
          "=r"((r)[20]), "=r"((r)[21]), "=r"((r)[22]), "=r"((r)[23]), \
          "=r"((r)[24]), "=r"((r)[25]), "=r"((r)[26]), "=r"((r)[27]), \
          "=r"((r)[28]), "=r"((r)[29]), "=r"((r)[30]), "=r"((r)[31]) \
        : "r"(tmem_addr))

// Multicast 2D TMA: delivers tile + complete_tx to every CTA in cta_mask.
#define TMA_LOAD_2D_MC(smem_addr, map, cx_, cy_, mbar, cta_mask) \
    asm volatile( \
        "cp.async.bulk.tensor.2d.shared::cluster.global.tile.mbarrier::complete_tx::bytes.multicast::cluster " \
        "[%0], [%1, {%2, %3}], [%4], %5;" \
        :: "r"((uint32_t)(smem_addr)), "l"(map), "r"((int)(cx_)), "r"((int)(cy_)), \
           "r"((uint32_t)(mbar)), "h"((uint16_t)(cta_mask)) : "memory")
#endif  // HAS_TCGEN05

// SW64 K-major smem descriptor (layout=4, version=1, SBO=32 (512B = 8 rows x 64B),
// LBO=1 (16B)). Rows are 64 bytes wide (BKT=32 fp16).
static constexpr uint64_t SMEM_DESC_BASE_SW64 =
    (uint64_t(4) << 61) | (uint64_t(1) << 46) | (uint64_t(32) << 32) | (uint64_t(1) << 16);
#define MAKE_SMEM_DESC64(base_addr) \
    (SMEM_DESC_BASE_SW64 | ((uint64_t)((base_addr) >> 4) & 0x3FFF))

#if HAS_TCGEN05
// SS f16 MMA, cg1: D[tmem] += A(desc) x B(desc)^T
__device__ __forceinline__ void mma_f16_ss(uint32_t d, uint64_t a, uint64_t b,
                                           uint32_t idesc, bool acc) {
    uint32_t en = acc ? 1u : 0u;
    asm volatile(
        "{\n\t.reg .pred p;\n\tsetp.ne.u32 p, %5, 0;\n\t"
        "tcgen05.mma.cta_group::1.kind::f16 [%0], %1, %2, %3, {%4, %4, %4, %4}, p;\n\t}"
        :: "r"(d), "l"(a), "l"(b), "r"(idesc), "r"(0u), "r"(en) : "memory");
}
#endif

// ===========================================================================
// dtype detection + conversion + dequant
// ===========================================================================
__device__ __forceinline__ int plausible(float v) {
    return (v == v) && (fabsf(v) < 16.0f) && (fabsf(v) > 5e-4f);
}

__global__ void detect_dtype_kernel(const void* __restrict__ x) {
    __shared__ int s[3];
    if (threadIdx.x < 3) s[threadIdx.x] = 0;
    __syncthreads();
    int c0 = 0, c1 = 0, c2 = 0;
    for (int i = threadIdx.x; i < 4096; i += blockDim.x) {
        c0 += plausible(__half2float(((const __half*)x)[i]));
        c1 += plausible(((const float*)x)[i]);
        c2 += plausible(__bfloat162float(((const __nv_bfloat16*)x)[i]));
    }
    atomicAdd(&s[0], c0); atomicAdd(&s[1], c1); atomicAdd(&s[2], c2);
    __syncthreads();
    if (threadIdx.x == 0) {
        int best = 0;
        if (s[1] > s[best]) best = 1;
        if (s[2] > s[best]) best = 2;
        g_dtype = best;
    }
}

__device__ __forceinline__ float load_elem(const void* p, size_t idx, int flag) {
    if (flag == 1) return ((const float*)p)[idx];
    if (flag == 2) return __bfloat162float(((const __nv_bfloat16*)p)[idx]);
    return __half2float(((const __half*)p)[idx]);
}

// Only runs real work when input is NOT fp16 (fp16 path feeds TMA directly from x).
__global__ void convert_x_kernel(const void* __restrict__ x) {
    const int flag = g_dtype;
    if (flag == 0) return;
    size_t base = ((size_t)blockIdx.x * blockDim.x + threadIdx.x) * 8;
    if (base >= (size_t)M_TOTAL * K_TOTAL) return;
    __half out[8];
    if (flag == 1) {
        const float4* fp = reinterpret_cast<const float4*>((const float*)x + base);
        float4 f0 = fp[0], f1 = fp[1];
        out[0] = __float2half(f0.x); out[1] = __float2half(f0.y);
        out[2] = __float2half(f0.z); out[3] = __float2half(f0.w);
        out[4] = __float2half(f1.x); out[5] = __float2half(f1.y);
        out[6] = __float2half(f1.z); out[7] = __float2half(f1.w);
    } else {
        uint4 raw = *reinterpret_cast<const uint4*>((const __nv_bfloat16*)x + base);
        const __nv_bfloat16* b = reinterpret_cast<const __nv_bfloat16*>(&raw);
#pragma unroll
        for (int i = 0; i < 8; i++) out[i] = __float2half(__bfloat162float(b[i]));
    }
    *reinterpret_cast<uint4*>(g_X + base) = *reinterpret_cast<uint4*>(out);
}

// 16 elements / thread (4 x 16B loads in flight, MLP=4)
__global__ void dequant_kernel(const int* __restrict__ Wq,
                               const void* __restrict__ scale,
                               const void* __restrict__ zero) {
    const int flag = g_dtype;
    size_t base = ((size_t)blockIdx.x * blockDim.x + threadIdx.x) * 16;
    if (base >= (size_t)N_TOTAL * K_TOTAL) return;
    int n = (int)(base / K_TOTAL);
    int k = (int)(base % K_TOTAL);
    int g = k / GROUP_SIZE;   // 16 | 128 so all 16 elems share the group
    __half s = __float2half(load_elem(scale, (size_t)n * NGROUPS + g, flag));
    __half z = __float2half(load_elem(zero,  (size_t)n * NGROUPS + g, flag));

    const int4* wp = reinterpret_cast<const int4*>(Wq + base);
    int4 w[4];
#pragma unroll
    for (int t = 0; t < 4; t++) w[t] = wp[t];

    __half out[16];
#pragma unroll
    for (int t = 0; t < 4; t++) {
        out[t*4+0] = __hmul(__hsub(__int2half_rn(w[t].x), z), s);
        out[t*4+1] = __hmul(__hsub(__int2half_rn(w[t].y), z), s);
        out[t*4+2] = __hmul(__hsub(__int2half_rn(w[t].z), z), s);
        out[t*4+3] = __hmul(__hsub(__int2half_rn(w[t].w), z), s);
    }
    uint4* op = reinterpret_cast<uint4*>(g_Wd + base);
    op[0] = reinterpret_cast<uint4*>(out)[0];
    op[1] = reinterpret_cast<uint4*>(out)[1];
}

// ===========================================================================
// tcgen05 GEMM, warp-specialized, cluster(2,2) TMA multicast, deep pipeline:
//   warp 0: MMA issuer; warp 1: TMA producer (A/B decoupled empties)
// CTA tile 256x256, K-stage 32 (SW64 rows), 6-stage pipeline, TMEM accum.
// ===========================================================================
#define BM 256
#define BN 256
#define BKT 32
#define NSTAGE 6
#define HALF_TILE_BYTES 8192          // 128 rows x 64B
#define MAT_STAGE_BYTES 16384         // one matrix tile: 256 rows x 64B
#define STAGE_BYTES 32768             // A(16KB) + B(16KB)

__global__ __launch_bounds__(128, 1) __cluster_dims__(2, 2, 1)
void gemm_tc(
    const __grid_constant__ CUtensorMap tmAx,   // A on x (fp16 input path)
    const __grid_constant__ CUtensorMap tmAg,   // A on g_X (converted path)
    const __grid_constant__ CUtensorMap tmB,
    const void* __restrict__ bias,
    void* __restrict__ C)
{
#if HAS_TCGEN05
    extern __shared__ __align__(1024) char smem[];
    const uint32_t sbase = smem_to_u32(smem);
    const uint32_t tbase = (sbase + 1024u) & ~1023u;   // tile region, 1024-aligned
    const int tid = threadIdx.x, wid = tid >> 5, lane = tid & 31;
    const int bm = blockIdx.y * BM, bn = blockIdx.x * BN;
    const int flag = g_dtype;
    const CUtensorMap* pA = (flag == 0) ? &tmAx : &tmAg;

    const int ccx = blockIdx.x & 1;               // cluster coords (rank = ccx + 2*ccy)
    const int ccy = blockIdx.y & 1;
    const uint16_t amask = (uint16_t)(0x3u << (2 * ccy));  // A-pair: same ccy
    const uint16_t bmask = (uint16_t)(0x5u << ccx);        // B-pair: same ccx

    const uint32_t full_mb = sbase + 8;            // 6 x 8B, count=2
    const uint32_t aemp_mb = full_mb + NSTAGE * 8; // 6 x 8B, count=2
    const uint32_t bemp_mb = aemp_mb + NSTAGE * 8; // 6 x 8B, count=2

    if (tid == 0) {
        for (int s = 0; s < NSTAGE; s++) {
            MBARRIER_INIT(full_mb + s * 8, 2);
            MBARRIER_INIT(aemp_mb + s * 8, 2);
            MBARRIER_INIT(bemp_mb + s * 8, 2);
        }
    }
    if (wid == 0) {
        TCGEN05_ALLOC(sbase, 512);
        TCGEN05_RELINQUISH();
    }
    __syncthreads();
    CLUSTER_SYNC();   // peers' barriers initialized before any multicast TMA
    uint32_t tmem;
    asm volatile("ld.shared.b32 %0, [%1];" : "=r"(tmem) : "r"(sbase));

    const int NKT = K_TOTAL / BKT;  // 128

    if (wid == 0) {
        // ---- MMA issuer warp: paced only by full[] and the HW dispatch queue
        const uint32_t idesc = (1u << 4) | (16u << 17) | (8u << 24);  // F32 acc, F16, N=128, M=128
        for (int kt = 0; kt < NKT; kt++) {
            const int s = kt % NSTAGE;
            const int r = kt / NSTAGE;
            MBARRIER_WAIT_PARITY(full_mb + s * 8, r & 1);
            if (elect_one_pred()) {
                const uint32_t aL = tbase + s * STAGE_BYTES;
                const uint32_t bL = aL + MAT_STAGE_BYTES;
                const uint64_t a0 = MAKE_SMEM_DESC64(aL);
                const uint64_t a1 = MAKE_SMEM_DESC64(aL + HALF_TILE_BYTES);
                const uint64_t b0 = MAKE_SMEM_DESC64(bL);
                const uint64_t b1 = MAKE_SMEM_DESC64(bL + HALF_TILE_BYTES);
#pragma unroll
                for (int ks = 0; ks < 2; ks++) {     // 2 K-steps of 16
                    const bool acc = !(kt == 0 && ks == 0);
                    mma_f16_ss(tmem + 0,   a0 + ks * 2, b0 + ks * 2, idesc, acc);
                    mma_f16_ss(tmem + 128, a0 + ks * 2, b1 + ks * 2, idesc, acc);
                    mma_f16_ss(tmem + 256, a1 + ks * 2, b0 + ks * 2, idesc, acc);
                    mma_f16_ss(tmem + 384, a1 + ks * 2, b1 + ks * 2, idesc, acc);
                }
                TCGEN05_COMMIT_MULTICAST(aemp_mb + s * 8, amask);
                TCGEN05_COMMIT_MULTICAST(bemp_mb + s * 8, bmask);
            }
        }
        // Drain: last kt = NKT-1 -> its empty barrier fires when both pair
        // CTAs' final commits (covering ALL their prior MMAs) complete.
        MBARRIER_WAIT_PARITY(aemp_mb + ((NKT - 1) % NSTAGE) * 8,
                             ((NKT - 1) / NSTAGE) & 1);
    } else if (wid == 1) {
        // ---- Producer warp: prologue fills all stages, then steady refills
        if (elect_one_pred()) {
#pragma unroll
            for (int s = 0; s < NSTAGE; s++) {
                MBARRIER_EXPECT_TX(full_mb + s * 8, MAT_STAGE_BYTES);
                if (ccx == 0)
                    TMA_LOAD_2D_MC(tbase + s * STAGE_BYTES, pA, s * BKT, bm,
                                   full_mb + s * 8, amask);
                MBARRIER_EXPECT_TX(full_mb + s * 8, MAT_STAGE_BYTES);
                if (ccy == 0)
                    TMA_LOAD_2D_MC(tbase + s * STAGE_BYTES + MAT_STAGE_BYTES, &tmB,
                                   s * BKT, bn, full_mb + s * 8, bmask);
            }
        }
        for (int kl = NSTAGE; kl < NKT; kl++) {
            const int s  = kl % NSTAGE;
            const int pe = ((kl / NSTAGE) - 1) & 1;   // parity of retired round
            MBARRIER_WAIT_PARITY(aemp_mb + s * 8, pe);
            if (elect_one_pred()) {
                MBARRIER_EXPECT_TX(full_mb + s * 8, MAT_STAGE_BYTES);
                if (ccx == 0)
                    TMA_LOAD_2D_MC(tbase + s * STAGE_BYTES, pA, kl * BKT, bm,
                                   full_mb + s * 8, amask);
            }
            MBARRIER_WAIT_PARITY(bemp_mb + s * 8, pe);
            if (elect_one_pred()) {
                MBARRIER_EXPECT_TX(full_mb + s * 8, MAT_STAGE_BYTES);
                if (ccy == 0)
                    TMA_LOAD_2D_MC(tbase + s * STAGE_BYTES + MAT_STAGE_BYTES, &tmB,
                                   kl * BKT, bn, full_mb + s * 8, bmask);
            }
        }
    }
    __syncthreads();
    TCGEN05_FENCE_AFTER();

    // Epilogue: 4 warps read TMEM quadrants, add bias, store
#pragma unroll
    for (int q = 0; q < 4; q++) {
        const int m  = bm + (q >> 1) * 128 + wid * 32 + lane;
        const int nb = bn + (q & 1) * 128;
#pragma unroll
        for (int j = 0; j < 4; j++) {
            uint32_t r[32];
            TCGEN05_LD_32X32B_X32(r, tmem + q * 128 + j * 32);
            TCGEN05_WAIT_LD();
            const int n0 = nb + j * 32;
            float v[32];
#pragma unroll
            for (int i = 0; i < 32; i++)
                v[i] = __uint_as_float(r[i]) + load_elem(bias, n0 + i, flag);
            const size_t off = (size_t)m * N_TOTAL + n0;
            if (flag == 1) {
                float4* o = reinterpret_cast<float4*>((float*)C + off);
#pragma unroll
                for (int t = 0; t < 8; t++)
                    o[t] = make_float4(v[t*4], v[t*4+1], v[t*4+2], v[t*4+3]);
            } else if (flag == 2) {
                __nv_bfloat16 h[32];
#pragma unroll
                for (int i = 0; i < 32; i++) h[i] = __float2bfloat16(v[i]);
                uint4* o = reinterpret_cast<uint4*>((__nv_bfloat16*)C + off);
#pragma unroll
                for (int t = 0; t < 4; t++) o[t] = reinterpret_cast<uint4*>(h)[t];
            } else {
                __half h[32];
#pragma unroll
                for (int i = 0; i < 32; i++) h[i] = __float2half(v[i]);
                uint4* o = reinterpret_cast<uint4*>((__half*)C + off);
#pragma unroll
                for (int t = 0; t < 4; t++) o[t] = reinterpret_cast<uint4*>(h)[t];
            }
        }
    }

    __syncthreads();
    TCGEN05_FENCE_BEFORE();
    if (wid == 0) TCGEN05_DEALLOC(tmem, 512);
    CLUSTER_SYNC();   // no CTA exits while peers' multicast may target its smem
#endif  // HAS_TCGEN05
}

// ===========================================================================
// Launch
// ===========================================================================
typedef CUresult (*EncodeTiledFn)(
    CUtensorMap*, CUtensorMapDataType, cuuint32_t, void*,
    const cuuint64_t*, const cuuint64_t*, const cuuint32_t*, const cuuint32_t*,
    CUtensorMapInterleave, CUtensorMapSwizzle, CUtensorMapL2promotion,
    CUtensorMapFloatOOBfill);

static void make_map_2d(EncodeTiledFn fn, CUtensorMap* m, void* base) {
    cuuint64_t dims[2]    = {K_TOTAL, 4096};                 // dim0 = K (contiguous)
    cuuint64_t strides[1] = {(cuuint64_t)K_TOTAL * 2};       // bytes per row
    cuuint32_t box[2]     = {BKT, BM};                        // 32 halves (64B) x 256 rows
    cuuint32_t estr[2]    = {1, 1};
    fn(m, CU_TENSOR_MAP_DATA_TYPE_FLOAT16, 2, base, dims, strides, box, estr,
       CU_TENSOR_MAP_INTERLEAVE_NONE, CU_TENSOR_MAP_SWIZZLE_64B,
       CU_TENSOR_MAP_L2_PROMOTION_L2_128B, CU_TENSOR_MAP_FLOAT_OOB_FILL_NONE);
}

#define GEMM_SMEM_BYTES (2048 + NSTAGE * STAGE_BYTES)   // 2KB slack + 192KB tiles

extern "C" void kernel_launch(void* const* d_in, const int* in_sizes, int n_in,
                              void* d_out, int out_size) {
    int ix = 0, iw = 1, is = 2, iz = 3, ib = 4;  // dict order default
    if (n_in >= 5 && in_sizes[1] == 4096) {      // alphabetical order
        iw = 0; ib = 1; is = 2; ix = 3; iz = 4;
    }
    const void* x     = d_in[ix];
    const int*  Wq    = (const int*)d_in[iw];
    const void* scale = d_in[is];
    const void* zero  = d_in[iz];
    const void* bias  = d_in[ib];

    detect_dtype_kernel<<<1, 256>>>(x);
    {
        size_t total8 = (size_t)M_TOTAL * K_TOTAL / 8;
        convert_x_kernel<<<(int)((total8 + 255) / 256), 256>>>(x);
    }
    {
        size_t total16 = (size_t)N_TOTAL * K_TOTAL / 16;
        dequant_kernel<<<(int)((total16 + 255) / 256), 256>>>(Wq, scale, zero);
    }

    void* pX = nullptr;
    void* pW = nullptr;
    cudaGetSymbolAddress(&pX, g_X);
    cudaGetSymbolAddress(&pW, g_Wd);

    EncodeTiledFn encode = nullptr;
    cudaDriverEntryPointQueryResult qr;
    cudaGetDriverEntryPointByVersion("cuTensorMapEncodeTiled", (void**)&encode,
                                     12000, cudaEnableDefault, &qr);

    CUtensorMap tmAx, tmAg, tmB;
    make_map_2d(encode, &tmAx, (void*)x);   // direct fp16-input path
    make_map_2d(encode, &tmAg, pX);         // converted path
    make_map_2d(encode, &tmB, pW);

    cudaFuncSetAttribute(gemm_tc, cudaFuncAttributeMaxDynamicSharedMemorySize,
                         GEMM_SMEM_BYTES);
    dim3 grid(N_TOTAL / BN, M_TOTAL / BM);
    gemm_tc<<<grid, 128, GEMM_SMEM_BYTES>>>(tmAx, tmAg, tmB, bias, d_out);
}

// round 9
// speedup vs baseline: 1.0682x; 1.0682x over previous
#include <cuda_runtime.h>
#include <cuda.h>
#include <cuda_fp16.h>
#include <cuda_bf16.h>
#include <cstdint>

#define M_TOTAL 4096
#define N_TOTAL 4096
#define K_TOTAL 4096
#define GROUP_SIZE 128
#define NGROUPS (K_TOTAL / GROUP_SIZE)   // 32

// Arch-specific feature gate (tcgen05/TMEM/TMA-multicast are sm_103a-only).
#if defined(__CUDA_ARCH_FEAT_SM103_ALL) || defined(__CUDA_ARCH_FEAT_SM100_ALL) || \
    (defined(__CUDA_ARCH_SPECIFIC__) && (__CUDA_ARCH_SPECIFIC__ >= 1000))
#define HAS_TCGEN05 1
#else
#define HAS_TCGEN05 0
#endif

// Scratch (device globals: allocation-free rule)
__device__ __half g_Wd[(size_t)N_TOTAL * K_TOTAL];   // dequantized weights fp16 [N,K]
__device__ __half g_X[(size_t)M_TOTAL * K_TOTAL];    // activations fp16 [M,K] (non-f16 input only)
__device__ int    g_dtype;                           // 0=f16, 1=f32, 2=bf16

// ===========================================================================
// PTX helpers
// ===========================================================================
__device__ __forceinline__ uint32_t elect_one_pred() {
    uint32_t pred;
    asm volatile(
        "{\n\t.reg .pred p;\n\telect.sync _|p, 0xFFFFFFFF;\n\t"
        "selp.b32 %0, 1, 0, p;\n\t}"
        : "=r"(pred));
    return pred;
}
__device__ __forceinline__ uint32_t smem_to_u32(const void* p) {
    uint32_t a;
    asm("{ .reg .u64 t; cvta.to.shared.u64 t, %1; cvt.u32.u64 %0, t; }" : "=r"(a) : "l"(p));
    return a;
}

#define MBARRIER_INIT(addr, cnt) \
    asm volatile("mbarrier.init.shared.b64 [%0], %1;" :: "r"((uint32_t)(addr)), "r"((uint32_t)(cnt)) : "memory")
#define MBARRIER_EXPECT_TX(addr, bytes) \
    asm volatile("mbarrier.arrive.expect_tx.shared.b64 _, [%0], %1;" :: "r"((uint32_t)(addr)), "r"((uint32_t)(bytes)) : "memory")

#define MBARRIER_WAIT_PARITY(mbar_addr, phase_parity) do { \
    uint32_t _mbar = (uint32_t)(mbar_addr); \
    uint32_t _par = (uint32_t)(phase_parity); \
    uint32_t _done; \
    asm volatile("{\n\t.reg .pred p;\n\t" \
        "mbarrier.try_wait.parity.acquire.cta.shared::cta.b64 p, [%1], %2;\n\t" \
        "selp.b32 %0, 1, 0, p;\n\t}" : "=r"(_done) : "r"(_mbar), "r"(_par) : "memory"); \
    if (!_done) { \
        asm volatile("{\n\t.reg .pred P1;\n\t" \
            "WAIT_LOOP_%=:\n\t" \
            "mbarrier.try_wait.parity.acquire.cta.shared::cta.b64 P1, [%0], %1, 0x989680;\n\t" \
            "@P1 bra.uni WAIT_DONE_%=;\n\t" \
            "bra.uni WAIT_LOOP_%=;\n\t" \
            "WAIT_DONE_%=:\n\t}" :: "r"(_mbar), "r"(_par) : "memory"); \
    } \
} while(0)

#define CLUSTER_SYNC() do { \
    asm volatile("barrier.cluster.arrive.aligned;" ::: "memory"); \
    asm volatile("barrier.cluster.wait.aligned;" ::: "memory"); \
} while(0)

#if HAS_TCGEN05
#define TCGEN05_ALLOC(smem_addr, nCols) \
    asm volatile("tcgen05.alloc.cta_group::1.sync.aligned.shared::cta.b32 [%0], %1;" \
        :: "r"((uint32_t)(smem_addr)), "r"((uint32_t)(nCols)) : "memory")
#define TCGEN05_DEALLOC(tmem_addr, nCols) \
    asm volatile("tcgen05.dealloc.cta_group::1.sync.aligned.b32 %0, %1;" :: "r"(tmem_addr), "r"((uint32_t)(nCols)))
#define TCGEN05_RELINQUISH() \
    asm volatile("tcgen05.relinquish_alloc_permit.cta_group::1.sync.aligned;")
#define TCGEN05_COMMIT_MULTICAST(mbar, mask) \
    asm volatile("tcgen05.commit.cta_group::1.mbarrier::arrive::one.shared::cluster.multicast::cluster.b64 [%0], %1;" \
        :: "r"((uint32_t)(mbar)), "h"((uint16_t)(mask)) : "memory")
#define TCGEN05_FENCE_AFTER() \
    asm volatile("tcgen05.fence::after_thread_sync;" ::: "memory")
#define TCGEN05_FENCE_BEFORE() \
    asm volatile("tcgen05.fence::before_thread_sync;" ::: "memory")
#define TCGEN05_WAIT_LD() \
    asm volatile("tcgen05.wait::ld.sync.aligned;" ::: "memory")

#define TCGEN05_LD_32X32B_X32(r, tmem_addr) \
    asm volatile( \
        "tcgen05.ld.sync.aligned.32x32b.x32.b32 " \
        "{%0, %1, %2, %3, %4, %5, %6, %7, " \
        " %8, %9, %10, %11, %12, %13, %14, %15, " \
        " %16, %17, %18, %19, %20, %21, %22, %23, " \
        " %24, %25, %26, %27, %28, %29, %30, %31}, [%32];" \
        : "=r"((r)[0]),  "=r"((r)[1]),  "=r"((r)[2]),  "=r"((r)[3]), \
          "=r"((r)[4]),  "=r"((r)[5]),  "=r"((r)[6]),  "=r"((r)[7]), \
          "=r"((r)[8]),  "=r"((r)[9]),  "=r"((r)[10]), "=r"((r)[11]), \
          "=r"((r)[12]), "=r"((r)[13]), "=r"((r)[14]), "=r"((r)[15]), \
          "=r"((r)[16]), "=r"((r)[17]), "=r"((r)[18]), "=r"((r)[19]), \
          "=r"((r)[20]), "=r"((r)[21]), "=r"((r)[22]), "=r"((r)[23]), \
          "=r"((r)[24]), "=r"((r)[25]), "=r"((r)[26]), "=r"((r)[27]), \
          "=r"((r)[28]), "=r"((r)[29]), "=r"((r)[30]), "=r"((r)[31]) \
        : "r"(tmem_addr))

// Multicast 2D TMA: delivers tile + complete_tx to every CTA in cta_mask.
#define TMA_LOAD_2D_MC(smem_addr, map, cx_, cy_, mbar, cta_mask) \
    asm volatile( \
        "cp.async.bulk.tensor.2d.shared::cluster.global.tile.mbarrier::complete_tx::bytes.multicast::cluster " \
        "[%0], [%1, {%2, %3}], [%4], %5;" \
        :: "r"((uint32_t)(smem_addr)), "l"(map), "r"((int)(cx_)), "r"((int)(cy_)), \
           "r"((uint32_t)(mbar)), "h"((uint16_t)(cta_mask)) : "memory")
#endif  // HAS_TCGEN05

// SW128 K-major smem descriptor (LBO=1, SBO=64, version=1, layout=2)
static constexpr uint64_t SMEM_DESC_BASE_SW128 =
    (uint64_t(2) << 61) | (uint64_t(1) << 46) | (uint64_t(64) << 32) | (uint64_t(1) << 16);
#define MAKE_SMEM_DESC(base_addr) \
    (SMEM_DESC_BASE_SW128 | ((uint64_t)((base_addr) >> 4) & 0x3FFF))

#if HAS_TCGEN05
// SS f16 MMA, cg1: D[tmem] += A(desc) x B(desc)^T
__device__ __forceinline__ void mma_f16_ss(uint32_t d, uint64_t a, uint64_t b,
                                           uint32_t idesc, bool acc) {
    uint32_t en = acc ? 1u : 0u;
    asm volatile(
        "{\n\t.reg .pred p;\n\tsetp.ne.u32 p, %5, 0;\n\t"
        "tcgen05.mma.cta_group::1.kind::f16 [%0], %1, %2, %3, {%4, %4, %4, %4}, p;\n\t}"
        :: "r"(d), "l"(a), "l"(b), "r"(idesc), "r"(0u), "r"(en) : "memory");
}
#endif

// ===========================================================================
// dtype detection
// ===========================================================================
__device__ __forceinline__ int plausible(float v) {
    return (v == v) && (fabsf(v) < 16.0f) && (fabsf(v) > 5e-4f);
}

__global__ void detect_dtype_kernel(const void* __restrict__ x) {
    __shared__ int s[3];
    if (threadIdx.x < 3) s[threadIdx.x] = 0;
    __syncthreads();
    int c0 = 0, c1 = 0, c2 = 0;
    for (int i = threadIdx.x; i < 4096; i += blockDim.x) {
        c0 += plausible(__half2float(((const __half*)x)[i]));
        c1 += plausible(((const float*)x)[i]);
        c2 += plausible(__bfloat162float(((const __nv_bfloat16*)x)[i]));
    }
    atomicAdd(&s[0], c0); atomicAdd(&s[1], c1); atomicAdd(&s[2], c2);
    __syncthreads();
    if (threadIdx.x == 0) {
        int best = 0;
        if (s[1] > s[best]) best = 1;
        if (s[2] > s[best]) best = 2;
        g_dtype = best;
    }
}

__device__ __forceinline__ float load_elem(const void* p, size_t idx, int flag) {
    if (flag == 1) return ((const float*)p)[idx];
    if (flag == 2) return __bfloat162float(((const __nv_bfloat16*)p)[idx]);
    return __half2float(((const __half*)p)[idx]);
}

// ===========================================================================
// Fused prep: blocks [0, NDQ) dequantize W_q -> g_Wd (16 elems/thread),
//             blocks [NDQ, NDQ+NCV) convert x -> g_X (no-op for fp16 input).
// ===========================================================================
#define DQ_BLOCKS  ((int)((size_t)N_TOTAL * K_TOTAL / 16 / 256))   // 4096
#define CV_BLOCKS  ((int)((size_t)M_TOTAL * K_TOTAL / 8  / 256))   // 8192

__global__ void prep_kernel(const int* __restrict__ Wq,
                            const void* __restrict__ scale,
                            const void* __restrict__ zero,
                            const void* __restrict__ x) {
    const int flag = g_dtype;
    if (blockIdx.x < DQ_BLOCKS) {
        // ---- dequant: W = (half(q) - zero[g]) * scale[g], fp16 math
        size_t base = ((size_t)blockIdx.x * blockDim.x + threadIdx.x) * 16;
        int n = (int)(base / K_TOTAL);
        int k = (int)(base % K_TOTAL);
        int g = k / GROUP_SIZE;   // 16 | 128 so all 16 elems share the group
        __half s = __float2half(load_elem(scale, (size_t)n * NGROUPS + g, flag));
        __half z = __float2half(load_elem(zero,  (size_t)n * NGROUPS + g, flag));

        const int4* wp = reinterpret_cast<const int4*>(Wq + base);
        int4 w[4];
#pragma unroll
        for (int t = 0; t < 4; t++) w[t] = wp[t];

        __half out[16];
#pragma unroll
        for (int t = 0; t < 4; t++) {
            out[t*4+0] = __hmul(__hsub(__int2half_rn(w[t].x), z), s);
            out[t*4+1] = __hmul(__hsub(__int2half_rn(w[t].y), z), s);
            out[t*4+2] = __hmul(__hsub(__int2half_rn(w[t].z), z), s);
            out[t*4+3] = __hmul(__hsub(__int2half_rn(w[t].w), z), s);
        }
        uint4* op = reinterpret_cast<uint4*>(g_Wd + base);
        op[0] = reinterpret_cast<uint4*>(out)[0];
        op[1] = reinterpret_cast<uint4*>(out)[1];
    } else {
        // ---- convert x (only when input is not fp16)
        if (flag == 0) return;
        size_t base = ((size_t)(blockIdx.x - DQ_BLOCKS) * blockDim.x + threadIdx.x) * 8;
        __half out[8];
        if (flag == 1) {
            const float4* fp = reinterpret_cast<const float4*>((const float*)x + base);
            float4 f0 = fp[0], f1 = fp[1];
            out[0] = __float2half(f0.x); out[1] = __float2half(f0.y);
            out[2] = __float2half(f0.z); out[3] = __float2half(f0.w);
            out[4] = __float2half(f1.x); out[5] = __float2half(f1.y);
            out[6] = __float2half(f1.z); out[7] = __float2half(f1.w);
        } else {
            uint4 raw = *reinterpret_cast<const uint4*>((const __nv_bfloat16*)x + base);
            const __nv_bfloat16* b = reinterpret_cast<const __nv_bfloat16*>(&raw);
#pragma unroll
            for (int i = 0; i < 8; i++) out[i] = __float2half(__bfloat162float(b[i]));
        }
        *reinterpret_cast<uint4*>(g_X + base) = *reinterpret_cast<uint4*>(out);
    }
}

// ===========================================================================
// tcgen05 GEMM, warp-specialized, cluster(2,2) TMA multicast:
//   warp 0: MMA issuer; warp 1: A producer; warp 2: B producer
// CTA tile 256x256, K-stage 64 (SW128), 3-stage pipeline, TMEM accumulators.
// ===========================================================================
#define BM 256
#define BN 256
#define BKT 64
#define NSTAGE 3
#define HALF_TILE_BYTES 16384         // 128 rows x 128B
#define MAT_STAGE_BYTES 32768         // one matrix tile: 256 rows x 128B
#define STAGE_BYTES 65536             // A(32KB) + B(32KB)

__global__ __launch_bounds__(128, 1) __cluster_dims__(2, 2, 1)
void gemm_tc(
    const __grid_constant__ CUtensorMap tmAx,   // A on x (fp16 input path)
    const __grid_constant__ CUtensorMap tmAg,   // A on g_X (converted path)
    const __grid_constant__ CUtensorMap tmB,
    const void* __restrict__ bias,
    void* __restrict__ C)
{
#if HAS_TCGEN05
    extern __shared__ __align__(1024) char smem[];
    const uint32_t sbase = smem_to_u32(smem);
    const uint32_t tbase = (sbase + 1024u) & ~1023u;   // tile region, 1024-aligned
    const int tid = threadIdx.x, wid = tid >> 5, lane = tid & 31;
    const int bm = blockIdx.y * BM, bn = blockIdx.x * BN;
    const int flag = g_dtype;
    const CUtensorMap* pA = (flag == 0) ? &tmAx : &tmAg;

    const int ccx = blockIdx.x & 1;               // cluster coords (rank = ccx + 2*ccy)
    const int ccy = blockIdx.y & 1;
    const uint16_t amask = (uint16_t)(0x3u << (2 * ccy));  // A-pair: same ccy
    const uint16_t bmask = (uint16_t)(0x5u << ccx);        // B-pair: same ccx

    const uint32_t full_mb = sbase + 8;            // 3 x 8B, count=2
    const uint32_t aemp_mb = full_mb + NSTAGE * 8; // 3 x 8B, count=2
    const uint32_t bemp_mb = aemp_mb + NSTAGE * 8; // 3 x 8B, count=2

    if (tid == 0) {
        for (int s = 0; s < NSTAGE; s++) {
            MBARRIER_INIT(full_mb + s * 8, 2);
            MBARRIER_INIT(aemp_mb + s * 8, 2);
            MBARRIER_INIT(bemp_mb + s * 8, 2);
        }
    }
    if (wid == 0) {
        TCGEN05_ALLOC(sbase, 512);
        TCGEN05_RELINQUISH();
    }
    __syncthreads();
    CLUSTER_SYNC();   // peers' barriers initialized before any multicast TMA
    uint32_t tmem;
    asm volatile("ld.shared.b32 %0, [%1];" : "=r"(tmem) : "r"(sbase));

    const int NKT = K_TOTAL / BKT;  // 64

    if (wid == 0) {
        // ---- MMA issuer warp: paced only by full[] and the HW dispatch queue
        const uint32_t idesc = (1u << 4) | (16u << 17) | (8u << 24);  // F32 acc, F16, N=128, M=128
        for (int kt = 0; kt < NKT; kt++) {
            const int s = kt % NSTAGE;
            const int r = kt / NSTAGE;
            MBARRIER_WAIT_PARITY(full_mb + s * 8, r & 1);
            if (elect_one_pred()) {
                const uint32_t aL = tbase + s * STAGE_BYTES;
                const uint32_t bL = aL + MAT_STAGE_BYTES;
                const uint64_t a0 = MAKE_SMEM_DESC(aL);
                const uint64_t a1 = MAKE_SMEM_DESC(aL + HALF_TILE_BYTES);
                const uint64_t b0 = MAKE_SMEM_DESC(bL);
                const uint64_t b1 = MAKE_SMEM_DESC(bL + HALF_TILE_BYTES);
#pragma unroll
                for (int ks = 0; ks < 4; ks++) {
                    const bool acc = !(kt == 0 && ks == 0);
                    mma_f16_ss(tmem + 0,   a0 + ks * 2, b0 + ks * 2, idesc, acc);
                    mma_f16_ss(tmem + 128, a0 + ks * 2, b1 + ks * 2, idesc, acc);
                    mma_f16_ss(tmem + 256, a1 + ks * 2, b0 + ks * 2, idesc, acc);
                    mma_f16_ss(tmem + 384, a1 + ks * 2, b1 + ks * 2, idesc, acc);
                }
                TCGEN05_COMMIT_MULTICAST(aemp_mb + s * 8, amask);
                TCGEN05_COMMIT_MULTICAST(bemp_mb + s * 8, bmask);
            }
        }
        // Drain: last stage's empty barrier fires when both pair CTAs'
        // final commits (covering ALL prior MMAs) complete.
        MBARRIER_WAIT_PARITY(aemp_mb + ((NKT - 1) % NSTAGE) * 8,
                             ((NKT - 1) / NSTAGE) & 1);
    } else if (wid == 1) {
        // ---- A producer warp (independent chain)
        if (elect_one_pred()) {
#pragma unroll
            for (int s = 0; s < NSTAGE; s++) {
                MBARRIER_EXPECT_TX(full_mb + s * 8, MAT_STAGE_BYTES);
                if (ccx == 0)
                    TMA_LOAD_2D_MC(tbase + s * STAGE_BYTES, pA, s * BKT, bm,
                                   full_mb + s * 8, amask);
            }
            for (int kl = NSTAGE; kl < NKT; kl++) {
                const int s  = kl % NSTAGE;
                const int pe = ((kl / NSTAGE) - 1) & 1;   // parity of retired round
                MBARRIER_WAIT_PARITY(aemp_mb + s * 8, pe);
                MBARRIER_EXPECT_TX(full_mb + s * 8, MAT_STAGE_BYTES);
                if (ccx == 0)
                    TMA_LOAD_2D_MC(tbase + s * STAGE_BYTES, pA, kl * BKT, bm,
                                   full_mb + s * 8, amask);
            }
        }
    } else if (wid == 2) {
        // ---- B producer warp (independent chain)
        if (elect_one_pred()) {
#pragma unroll
            for (int s = 0; s < NSTAGE; s++) {
                MBARRIER_EXPECT_TX(full_mb + s * 8, MAT_STAGE_BYTES);
                if (ccy == 0)
                    TMA_LOAD_2D_MC(tbase + s * STAGE_BYTES + MAT_STAGE_BYTES, &tmB,
                                   s * BKT, bn, full_mb + s * 8, bmask);
            }
            for (int kl = NSTAGE; kl < NKT; kl++) {
                const int s  = kl % NSTAGE;
                const int pe = ((kl / NSTAGE) - 1) & 1;
                MBARRIER_WAIT_PARITY(bemp_mb + s * 8, pe);
                MBARRIER_EXPECT_TX(full_mb + s * 8, MAT_STAGE_BYTES);
                if (ccy == 0)
                    TMA_LOAD_2D_MC(tbase + s * STAGE_BYTES + MAT_STAGE_BYTES, &tmB,
                                   kl * BKT, bn, full_mb + s * 8, bmask);
            }
        }
    }
    __syncthreads();
    TCGEN05_FENCE_AFTER();

    // Epilogue: 4 warps read TMEM quadrants, add bias, store
#pragma unroll
    for (int q = 0; q < 4; q++) {
        const int m  = bm + (q >> 1) * 128 + wid * 32 + lane;
        const int nb = bn + (q & 1) * 128;
#pragma unroll
        for (int j = 0; j < 4; j++) {
            uint32_t r[32];
            TCGEN05_LD_32X32B_X32(r, tmem + q * 128 + j * 32);
            TCGEN05_WAIT_LD();
            const int n0 = nb + j * 32;
            float v[32];
#pragma unroll
            for (int i = 0; i < 32; i++)
                v[i] = __uint_as_float(r[i]) + load_elem(bias, n0 + i, flag);
            const size_t off = (size_t)m * N_TOTAL + n0;
            if (flag == 1) {
                float4* o = reinterpret_cast<float4*>((float*)C + off);
#pragma unroll
                for (int t = 0; t < 8; t++)
                    o[t] = make_float4(v[t*4], v[t*4+1], v[t*4+2], v[t*4+3]);
            } else if (flag == 2) {
                __nv_bfloat16 h[32];
#pragma unroll
                for (int i = 0; i < 32; i++) h[i] = __float2bfloat16(v[i]);
                uint4* o = reinterpret_cast<uint4*>((__nv_bfloat16*)C + off);
#pragma unroll
                for (int t = 0; t < 4; t++) o[t] = reinterpret_cast<uint4*>(h)[t];
            } else {
                __half h[32];
#pragma unroll
                for (int i = 0; i < 32; i++) h[i] = __float2half(v[i]);
                uint4* o = reinterpret_cast<uint4*>((__half*)C + off);
#pragma unroll
                for (int t = 0; t < 4; t++) o[t] = reinterpret_cast<uint4*>(h)[t];
            }
        }
    }

    __syncthreads();
    TCGEN05_FENCE_BEFORE();
    if (wid == 0) TCGEN05_DEALLOC(tmem, 512);
    CLUSTER_SYNC();   // no CTA exits while peers' multicast may target its smem
#endif  // HAS_TCGEN05
}

// ===========================================================================
// Launch
// ===========================================================================
typedef CUresult (*EncodeTiledFn)(
    CUtensorMap*, CUtensorMapDataType, cuuint32_t, void*,
    const cuuint64_t*, const cuuint64_t*, const cuuint32_t*, const cuuint32_t*,
    CUtensorMapInterleave, CUtensorMapSwizzle, CUtensorMapL2promotion,
    CUtensorMapFloatOOBfill);

static void make_map_2d(EncodeTiledFn fn, CUtensorMap* m, void* base) {
    cuuint64_t dims[2]    = {K_TOTAL, 4096};                 // dim0 = K (contiguous)
    cuuint64_t strides[1] = {(cuuint64_t)K_TOTAL * 2};       // bytes per row
    cuuint32_t box[2]     = {BKT, BM};                        // 64 halves (128B) x 256 rows
    cuuint32_t estr[2]    = {1, 1};
    fn(m, CU_TENSOR_MAP_DATA_TYPE_FLOAT16, 2, base, dims, strides, box, estr,
       CU_TENSOR_MAP_INTERLEAVE_NONE, CU_TENSOR_MAP_SWIZZLE_128B,
       CU_TENSOR_MAP_L2_PROMOTION_L2_128B, CU_TENSOR_MAP_FLOAT_OOB_FILL_NONE);
}

#define GEMM_SMEM_BYTES (2048 + NSTAGE * STAGE_BYTES)   // 2KB slack + 192KB tiles

extern "C" void kernel_launch(void* const* d_in, const int* in_sizes, int n_in,
                              void* d_out, int out_size) {
    int ix = 0, iw = 1, is = 2, iz = 3, ib = 4;  // dict order default
    if (n_in >= 5 && in_sizes[1] == 4096) {      // alphabetical order
        iw = 0; ib = 1; is = 2; ix = 3; iz = 4;
    }
    const void* x     = d_in[ix];
    const int*  Wq    = (const int*)d_in[iw];
    const void* scale = d_in[is];
    const void* zero  = d_in[iz];
    const void* bias  = d_in[ib];

    detect_dtype_kernel<<<1, 256>>>(x);
    prep_kernel<<<DQ_BLOCKS + CV_BLOCKS, 256>>>(Wq, scale, zero, x);

    void* pX = nullptr;
    void* pW = nullptr;
    cudaGetSymbolAddress(&pX, g_X);
    cudaGetSymbolAddress(&pW, g_Wd);

    EncodeTiledFn encode = nullptr;
    cudaDriverEntryPointQueryResult qr;
    cudaGetDriverEntryPointByVersion("cuTensorMapEncodeTiled", (void**)&encode,
                                     12000, cudaEnableDefault, &qr);

    CUtensorMap tmAx, tmAg, tmB;
    make_map_2d(encode, &tmAx, (void*)x);   // direct fp16-input path
    make_map_2d(encode, &tmAg, pX);         // converted path
    make_map_2d(encode, &tmB, pW);

    cudaFuncSetAttribute(gemm_tc, cudaFuncAttributeMaxDynamicSharedMemorySize,
                         GEMM_SMEM_BYTES);
    dim3 grid(N_TOTAL / BN, M_TOTAL / BM);
    gemm_tc<<<grid, 128, GEMM_SMEM_BYTES>>>(tmAx, tmAg, tmB, bias, d_out);
}